// round 1
// baseline (speedup 1.0000x reference)
#include <cuda_runtime.h>

#define D_DIM 256
#define K_DIM 1024
#define N_ROWS 32768
#define TM 16
#define NTHR 256

// Scratch (static device allocations are allowed)
__device__ float g_normC [K_DIM * D_DIM];   // normalized codebook, row-major [K][D]
__device__ float g_normCT[D_DIM * K_DIM];   // transposed [D][K] for coalesced logits loads
__device__ float g_colsum[K_DIM];
__device__ float g_lse_sum;

// ---------------------------------------------------------------------------
// Kernel 1: normalize codebook rows, write both layouts; block 0 zeroes accums
// ---------------------------------------------------------------------------
__global__ void k_prep(const float* __restrict__ cb) {
    int lane  = threadIdx.x & 31;
    int gwarp = (blockIdx.x * blockDim.x + threadIdx.x) >> 5;
    if (blockIdx.x == 0) {
        for (int k = threadIdx.x; k < K_DIM; k += blockDim.x) g_colsum[k] = 0.0f;
        if (threadIdx.x == 0) g_lse_sum = 0.0f;
    }
    if (gwarp >= K_DIM) return;
    const float* row = cb + (size_t)gwarp * D_DIM;
    float v[8]; float ss = 0.0f;
#pragma unroll
    for (int j = 0; j < 8; j++) { v[j] = row[lane + 32 * j]; ss += v[j] * v[j]; }
#pragma unroll
    for (int o = 16; o > 0; o >>= 1) ss += __shfl_xor_sync(0xffffffffu, ss, o);
    float rinv = rsqrtf(ss);
#pragma unroll
    for (int j = 0; j < 8; j++) {
        int d = lane + 32 * j;
        float nv = v[j] * rinv;
        g_normC [gwarp * D_DIM + d] = nv;
        g_normCT[d * K_DIM + gwarp] = nv;
    }
}

// ---------------------------------------------------------------------------
// Kernel 2: fused  normalize-rows -> logits GEMM -> softmax -> stats -> recon
// One CTA handles TM=16 rows. distances tile lives entirely in SMEM.
// ---------------------------------------------------------------------------
extern __shared__ float s_buf[];

__global__ __launch_bounds__(NTHR, 2) void k_main(const float* __restrict__ in,
                                                  float* __restrict__ out) {
    float* xs = s_buf;                    // [TM][D]   16 KB
    float* ds = s_buf + TM * D_DIM;       // [TM][K]   64 KB (logits -> distances)
    __shared__ float s_lse;
    const int tid  = threadIdx.x;
    const int warp = tid >> 5, lane = tid & 31;
    const size_t base = (size_t)blockIdx.x * TM * D_DIM;

    if (tid == 0) s_lse = 0.0f;
    for (int i = tid; i < TM * D_DIM; i += NTHR) xs[i] = in[base + i];
    __syncthreads();

    // normalize the 16 input rows: warp w -> rows 2w, 2w+1
#pragma unroll
    for (int rr = 0; rr < 2; rr++) {
        int r = warp * 2 + rr;
        float ss = 0.0f;
#pragma unroll
        for (int j = 0; j < 8; j++) { float v = xs[r * D_DIM + lane + 32 * j]; ss += v * v; }
#pragma unroll
        for (int o = 16; o > 0; o >>= 1) ss += __shfl_xor_sync(0xffffffffu, ss, o);
        float rinv = rsqrtf(ss);
#pragma unroll
        for (int j = 0; j < 8; j++) xs[r * D_DIM + lane + 32 * j] *= rinv;
    }
    __syncthreads();

    // ---- logits GEMM: [16 rows] x [1024 k].  Warp w owns k in [128w,128w+128),
    // lane holds 4 k's (stride 32). Codebook read from transposed layout: coalesced.
    float acc[TM][4];
#pragma unroll
    for (int r = 0; r < TM; r++)
#pragma unroll
        for (int j = 0; j < 4; j++) acc[r][j] = 0.0f;

    const int kb = warp * 128 + lane;
    const float* __restrict__ ct = g_normCT;
#pragma unroll 2
    for (int d = 0; d < D_DIM; d++) {
        float c0 = ct[d * K_DIM + kb];
        float c1 = ct[d * K_DIM + kb + 32];
        float c2 = ct[d * K_DIM + kb + 64];
        float c3 = ct[d * K_DIM + kb + 96];
#pragma unroll
        for (int r = 0; r < TM; r++) {
            float xv = xs[r * D_DIM + d];
            acc[r][0] = fmaf(xv, c0, acc[r][0]);
            acc[r][1] = fmaf(xv, c1, acc[r][1]);
            acc[r][2] = fmaf(xv, c2, acc[r][2]);
            acc[r][3] = fmaf(xv, c3, acc[r][3]);
        }
    }
#pragma unroll
    for (int r = 0; r < TM; r++)
#pragma unroll
        for (int j = 0; j < 4; j++) ds[r * K_DIM + kb + 32 * j] = acc[r][j];
    __syncthreads();

    // ---- softmax + second-softmax LSE stats.  warp w -> rows 2w, 2w+1.
    // max of dist row == 1/s1 exactly (softmax peak), so lse = 1/s1 + log(s2).
#pragma unroll
    for (int rr = 0; rr < 2; rr++) {
        int r = warp * 2 + rr;
        float* row = ds + r * K_DIM;
        float m = -1e30f;
#pragma unroll
        for (int j = 0; j < 32; j++) m = fmaxf(m, row[lane + 32 * j]);
#pragma unroll
        for (int o = 16; o > 0; o >>= 1) m = fmaxf(m, __shfl_xor_sync(0xffffffffu, m, o));
        float s = 0.0f;
#pragma unroll
        for (int j = 0; j < 32; j++) s += __expf(row[lane + 32 * j] - m);
#pragma unroll
        for (int o = 16; o > 0; o >>= 1) s += __shfl_xor_sync(0xffffffffu, s, o);
        float inv = 1.0f / s;                 // == max_k dist[r][k]
        float s2 = 0.0f;
#pragma unroll
        for (int j = 0; j < 32; j++) {
            float e = __expf(row[lane + 32 * j] - m) * inv;
            row[lane + 32 * j] = e;
            s2 += __expf(e - inv);
        }
#pragma unroll
        for (int o = 16; o > 0; o >>= 1) s2 += __shfl_xor_sync(0xffffffffu, s2, o);
        if (lane == 0) atomicAdd(&s_lse, inv + __logf(s2));
    }
    __syncthreads();

    // ---- column sums (for ||colsum||^2 term) + per-CTA lse flush
    for (int k = tid; k < K_DIM; k += NTHR) {
        float s = 0.0f;
#pragma unroll
        for (int r = 0; r < TM; r++) s += ds[r * K_DIM + k];
        atomicAdd(&g_colsum[k], s);
    }
    if (tid == 0) atomicAdd(&g_lse_sum, s_lse);

    // ---- reconstruction GEMM: [16,1024] @ [1024,256]. thread tid owns column tid.
    float acc2[TM];
#pragma unroll
    for (int r = 0; r < TM; r++) acc2[r] = 0.0f;
    const float* __restrict__ cn = g_normC;
    for (int k = 0; k < K_DIM; k += 4) {
        float c0 = cn[(k + 0) * D_DIM + tid];
        float c1 = cn[(k + 1) * D_DIM + tid];
        float c2 = cn[(k + 2) * D_DIM + tid];
        float c3 = cn[(k + 3) * D_DIM + tid];
#pragma unroll
        for (int r = 0; r < TM; r++) {
            float4 dv = *reinterpret_cast<const float4*>(&ds[r * K_DIM + k]);
            acc2[r] = fmaf(dv.x, c0, acc2[r]);
            acc2[r] = fmaf(dv.y, c1, acc2[r]);
            acc2[r] = fmaf(dv.z, c2, acc2[r]);
            acc2[r] = fmaf(dv.w, c3, acc2[r]);
        }
    }
#pragma unroll
    for (int r = 0; r < TM; r++) out[base + r * D_DIM + tid] = acc2[r];
}

// ---------------------------------------------------------------------------
// Kernel 3: finalize loss.  l1 == 1/K exactly (softmax rows sum to 1).
// entropy = sum_i lse_i - ||colsum||^2 / N
// ---------------------------------------------------------------------------
__global__ void k_loss(float* __restrict__ out, int out_size) {
    __shared__ float red[8];
    int tid = threadIdx.x;
    float s = 0.0f;
    for (int k = tid; k < K_DIM; k += 256) { float c = g_colsum[k]; s += c * c; }
#pragma unroll
    for (int o = 16; o > 0; o >>= 1) s += __shfl_xor_sync(0xffffffffu, s, o);
    if ((tid & 31) == 0) red[tid >> 5] = s;
    __syncthreads();
    if (tid == 0) {
        float t = 0.0f;
#pragma unroll
        for (int w = 0; w < 8; w++) t += red[w];
        float entropy = g_lse_sum - t / (float)N_ROWS;
        float loss = 1000.0f * (1.0f / (float)K_DIM) + 5e-5f * entropy;
        out[out_size - 1] = loss;
    }
}

extern "C" void kernel_launch(void* const* d_in, const int* in_sizes, int n_in,
                              void* d_out, int out_size) {
    const float* in = (const float*)d_in[0];
    const float* cb = (const float*)d_in[1];
    float* out = (float*)d_out;
    (void)in_sizes; (void)n_in;

    const size_t smem = (size_t)(TM * D_DIM + TM * K_DIM) * sizeof(float);
    cudaFuncSetAttribute(k_main, cudaFuncAttributeMaxDynamicSharedMemorySize, (int)smem);

    k_prep<<<K_DIM / 8, 256>>>(cb);
    k_main<<<N_ROWS / TM, NTHR, smem>>>(in, out);
    k_loss<<<1, 256>>>(out, out_size);
}

// round 2
// speedup vs baseline: 2.3100x; 2.3100x over previous
#include <cuda_runtime.h>
#include <cstdint>

#define D_DIM 256
#define K_DIM 1024
#define N_ROWS 32768
#define TM 32
#define NTHR 256
#define XS_STRIDE 260     // mod 32 = 4  -> conflict-free A frags
#define DS_STRIDE 1028    // mod 32 = 4  -> conflict-free A frags / colsum
#define STG_L 1032        // mod 32 = 8  -> conflict-free logits B frags
#define STG_R 264         // mod 32 = 8  -> conflict-free recon  B frags
#define STG_FLOATS 8448   // max(8*1032=8256, 32*264=8448)

__device__ float g_normC [K_DIM * D_DIM];   // normalized codebook (tf32 bits), [K][D]
__device__ float g_normCT[D_DIM * K_DIM];   // transposed (tf32 bits), [D][K]
__device__ float g_colsum[K_DIM];
__device__ float g_lse_sum;

__device__ __forceinline__ uint32_t f2tf32(float f) {
    uint32_t u;
    asm("cvt.rna.tf32.f32 %0, %1;" : "=r"(u) : "f"(f));
    return u;
}

__device__ __forceinline__ void mma8(float* c, const uint32_t* a, uint32_t b0, uint32_t b1) {
    asm volatile(
        "mma.sync.aligned.m16n8k8.row.col.f32.tf32.tf32.f32 "
        "{%0,%1,%2,%3}, {%4,%5,%6,%7}, {%8,%9}, {%0,%1,%2,%3};"
        : "+f"(c[0]), "+f"(c[1]), "+f"(c[2]), "+f"(c[3])
        : "r"(a[0]), "r"(a[1]), "r"(a[2]), "r"(a[3]), "r"(b0), "r"(b1));
}

// ---------------------------------------------------------------------------
// Kernel 1: normalize codebook rows -> tf32, write both layouts; zero accums
// ---------------------------------------------------------------------------
__global__ void k_prep(const float* __restrict__ cb) {
    int lane  = threadIdx.x & 31;
    int gwarp = (blockIdx.x * blockDim.x + threadIdx.x) >> 5;
    if (blockIdx.x == 0) {
        for (int k = threadIdx.x; k < K_DIM; k += blockDim.x) g_colsum[k] = 0.0f;
        if (threadIdx.x == 0) g_lse_sum = 0.0f;
    }
    if (gwarp >= K_DIM) return;
    const float* row = cb + (size_t)gwarp * D_DIM;
    float v[8]; float ss = 0.0f;
#pragma unroll
    for (int j = 0; j < 8; j++) { v[j] = row[lane + 32 * j]; ss += v[j] * v[j]; }
#pragma unroll
    for (int o = 16; o > 0; o >>= 1) ss += __shfl_xor_sync(0xffffffffu, ss, o);
    float rinv = rsqrtf(ss);
#pragma unroll
    for (int j = 0; j < 8; j++) {
        int d = lane + 32 * j;
        float nv = __uint_as_float(f2tf32(v[j] * rinv));
        g_normC [gwarp * D_DIM + d] = nv;
        g_normCT[d * K_DIM + gwarp] = nv;
    }
}

// ---------------------------------------------------------------------------
// Kernel 2: fused normalize -> TF32 MMA logits -> softmax+stats -> TF32 MMA recon
// One CTA = 32 rows.  8 warps.  All fragment SMEM accesses bank-conflict-free.
// ---------------------------------------------------------------------------
extern __shared__ float s_buf[];

__global__ __launch_bounds__(NTHR, 1) void k_main(const float* __restrict__ in,
                                                  float* __restrict__ out) {
    float* xs  = s_buf;                          // [32][260]
    float* ds  = xs + TM * XS_STRIDE;            // [32][1028]  exp -> distances(tf32)
    float* stg = ds + TM * DS_STRIDE;            // staging (codebook chunks)
    __shared__ float s_rowsum[TM];
    __shared__ float s_inv[TM];
    __shared__ float s_lse;

    const int tid  = threadIdx.x;
    const int warp = tid >> 5, lane = tid & 31;
    const int qr = lane >> 2, qc = lane & 3;     // quad row / col (mma frags)
    const size_t base = (size_t)blockIdx.x * TM * D_DIM;

    if (tid < TM) s_rowsum[tid] = 0.0f;
    if (tid == 0) s_lse = 0.0f;
    for (int i = tid; i < TM * D_DIM; i += NTHR) {
        int r = i >> 8, c = i & 255;
        xs[r * XS_STRIDE + c] = in[base + i];
    }
    __syncthreads();

    // normalize the 32 rows (warp w -> rows 4w..4w+3), round to tf32
#pragma unroll
    for (int rr = 0; rr < 4; rr++) {
        int r = warp * 4 + rr;
        float ss = 0.0f;
#pragma unroll
        for (int j = 0; j < 8; j++) { float v = xs[r * XS_STRIDE + lane + 32 * j]; ss += v * v; }
#pragma unroll
        for (int o = 16; o > 0; o >>= 1) ss += __shfl_xor_sync(0xffffffffu, ss, o);
        float rinv = rsqrtf(ss);
#pragma unroll
        for (int j = 0; j < 8; j++) {
            int idx = r * XS_STRIDE + lane + 32 * j;
            xs[idx] = __uint_as_float(f2tf32(xs[idx] * rinv));
        }
    }
    __syncthreads();

    // ---- logits: L[32,1024] = X[32,256] @ CT[256,1024], warp w owns n [128w,128w+128)
    float acc[2][16][4];
#pragma unroll
    for (int mt = 0; mt < 2; mt++)
#pragma unroll
        for (int nt = 0; nt < 16; nt++)
#pragma unroll
            for (int j = 0; j < 4; j++) acc[mt][nt][j] = 0.0f;

    for (int kd = 0; kd < D_DIM; kd += 8) {
        // stage CT rows kd..kd+7, all 1024 cols
#pragma unroll
        for (int jj = 0; jj < 8; jj++) {
            int f = jj * NTHR + tid;
            int j = f >> 8, c4 = (f & 255) << 2;
            float4 v = *reinterpret_cast<const float4*>(g_normCT + (size_t)(kd + j) * K_DIM + c4);
            *reinterpret_cast<float4*>(stg + j * STG_L + c4) = v;
        }
        __syncthreads();

        uint32_t a[2][4];
#pragma unroll
        for (int mt = 0; mt < 2; mt++) {
            const float* xr = xs + (mt * 16 + qr) * XS_STRIDE + kd + qc;
            a[mt][0] = __float_as_uint(xr[0]);
            a[mt][1] = __float_as_uint(xr[8 * XS_STRIDE]);
            a[mt][2] = __float_as_uint(xr[4]);
            a[mt][3] = __float_as_uint(xr[8 * XS_STRIDE + 4]);
        }
#pragma unroll
        for (int nt = 0; nt < 16; nt++) {
            int n0 = warp * 128 + nt * 8 + qr;
            uint32_t b0 = __float_as_uint(stg[qc * STG_L + n0]);
            uint32_t b1 = __float_as_uint(stg[(qc + 4) * STG_L + n0]);
            mma8(acc[0][nt], a[0], b0, b1);
            mma8(acc[1][nt], a[1], b0, b1);
        }
        __syncthreads();
    }

    // ---- exp (no max needed: logits are cosines in [-1,1]) + row partial sums
    float pr[2][2] = {{0.0f, 0.0f}, {0.0f, 0.0f}};
#pragma unroll
    for (int mt = 0; mt < 2; mt++)
#pragma unroll
        for (int nt = 0; nt < 16; nt++) {
            int col = warp * 128 + nt * 8 + 2 * qc;
            int r0  = mt * 16 + qr;
            float e0 = __expf(acc[mt][nt][0]);
            float e1 = __expf(acc[mt][nt][1]);
            float e2 = __expf(acc[mt][nt][2]);
            float e3 = __expf(acc[mt][nt][3]);
            *reinterpret_cast<float2*>(ds + r0 * DS_STRIDE + col)       = make_float2(e0, e1);
            *reinterpret_cast<float2*>(ds + (r0 + 8) * DS_STRIDE + col) = make_float2(e2, e3);
            pr[mt][0] += e0 + e1;
            pr[mt][1] += e2 + e3;
        }
#pragma unroll
    for (int o = 1; o <= 2; o <<= 1) {
        pr[0][0] += __shfl_xor_sync(0xffffffffu, pr[0][0], o);
        pr[0][1] += __shfl_xor_sync(0xffffffffu, pr[0][1], o);
        pr[1][0] += __shfl_xor_sync(0xffffffffu, pr[1][0], o);
        pr[1][1] += __shfl_xor_sync(0xffffffffu, pr[1][1], o);
    }
    if (qc == 0) {
        atomicAdd(&s_rowsum[qr],      pr[0][0]);
        atomicAdd(&s_rowsum[qr + 8],  pr[0][1]);
        atomicAdd(&s_rowsum[qr + 16], pr[1][0]);
        atomicAdd(&s_rowsum[qr + 24], pr[1][1]);
    }
    __syncthreads();
    if (tid < TM) s_inv[tid] = 1.0f / s_rowsum[tid];
    __syncthreads();

    // ---- normalize -> tf32 distances; Taylor LSE of distances:
    //      sum_k exp(d) = 1024 + sum(d) + t2/2 + t3/6 = 1025 + t2/2 + t3/6
    {
        int r = tid >> 3, seg = tid & 7;
        float inv = s_inv[r];
        float t2 = 0.0f, t3 = 0.0f;
        float* row = ds + r * DS_STRIDE;
#pragma unroll 4
        for (int i = 0; i < 32; i++) {
            float4* p = reinterpret_cast<float4*>(row + ((seg + 8 * i) << 2));
            float4 v = *p;
            v.x = __uint_as_float(f2tf32(v.x * inv));
            v.y = __uint_as_float(f2tf32(v.y * inv));
            v.z = __uint_as_float(f2tf32(v.z * inv));
            v.w = __uint_as_float(f2tf32(v.w * inv));
            *p = v;
            t2 += v.x * v.x + v.y * v.y + v.z * v.z + v.w * v.w;
            t3 += v.x * v.x * v.x + v.y * v.y * v.y + v.z * v.z * v.z + v.w * v.w * v.w;
        }
#pragma unroll
        for (int o = 1; o <= 4; o <<= 1) {
            t2 += __shfl_xor_sync(0xffffffffu, t2, o);
            t3 += __shfl_xor_sync(0xffffffffu, t3, o);
        }
        if (seg == 0)
            atomicAdd(&s_lse, __logf(1025.0f + 0.5f * t2 + 0.16666667f * t3));
    }
    __syncthreads();

    // ---- column sums + lse flush
#pragma unroll
    for (int j = 0; j < 4; j++) {
        int k = tid + j * 256;
        float s = 0.0f;
#pragma unroll
        for (int r = 0; r < TM; r++) s += ds[r * DS_STRIDE + k];
        atomicAdd(&g_colsum[k], s);
    }
    if (tid == 0) atomicAdd(&g_lse_sum, s_lse);

    // ---- recon: R[32,256] = dist[32,1024] @ C[1024,256], warp w owns n [32w,32w+32)
    float acc2[2][4][4];
#pragma unroll
    for (int mt = 0; mt < 2; mt++)
#pragma unroll
        for (int nt = 0; nt < 4; nt++)
#pragma unroll
            for (int j = 0; j < 4; j++) acc2[mt][nt][j] = 0.0f;

    for (int k0 = 0; k0 < K_DIM; k0 += 32) {
        // stage C rows k0..k0+31, all 256 cols
#pragma unroll
        for (int jj = 0; jj < 8; jj++) {
            int f = jj * NTHR + tid;
            int j = f >> 6, c4 = (f & 63) << 2;
            float4 v = *reinterpret_cast<const float4*>(g_normC + (size_t)(k0 + j) * D_DIM + c4);
            *reinterpret_cast<float4*>(stg + j * STG_R + c4) = v;
        }
        __syncthreads();

#pragma unroll
        for (int ks = 0; ks < 4; ks++) {
            int kk = ks * 8;
            uint32_t a[2][4];
#pragma unroll
            for (int mt = 0; mt < 2; mt++) {
                const float* dr = ds + (mt * 16 + qr) * DS_STRIDE + k0 + kk + qc;
                a[mt][0] = __float_as_uint(dr[0]);
                a[mt][1] = __float_as_uint(dr[8 * DS_STRIDE]);
                a[mt][2] = __float_as_uint(dr[4]);
                a[mt][3] = __float_as_uint(dr[8 * DS_STRIDE + 4]);
            }
#pragma unroll
            for (int nt = 0; nt < 4; nt++) {
                int n0 = warp * 32 + nt * 8 + qr;
                uint32_t b0 = __float_as_uint(stg[(kk + qc) * STG_R + n0]);
                uint32_t b1 = __float_as_uint(stg[(kk + qc + 4) * STG_R + n0]);
                mma8(acc2[0][nt], a[0], b0, b1);
                mma8(acc2[1][nt], a[1], b0, b1);
            }
        }
        __syncthreads();
    }

    // ---- write reconstruction
#pragma unroll
    for (int mt = 0; mt < 2; mt++)
#pragma unroll
        for (int nt = 0; nt < 4; nt++) {
            int r0  = mt * 16 + qr;
            int col = warp * 32 + nt * 8 + 2 * qc;
            *reinterpret_cast<float2*>(out + base + (size_t)r0 * D_DIM + col) =
                make_float2(acc2[mt][nt][0], acc2[mt][nt][1]);
            *reinterpret_cast<float2*>(out + base + (size_t)(r0 + 8) * D_DIM + col) =
                make_float2(acc2[mt][nt][2], acc2[mt][nt][3]);
        }
}

// ---------------------------------------------------------------------------
// Kernel 3: finalize loss.  l1 == 1/K exactly.
// entropy = sum_i lse_i - ||colsum||^2 / N
// ---------------------------------------------------------------------------
__global__ void k_loss(float* __restrict__ out, int out_size) {
    __shared__ float red[8];
    int tid = threadIdx.x;
    float s = 0.0f;
    for (int k = tid; k < K_DIM; k += 256) { float c = g_colsum[k]; s += c * c; }
#pragma unroll
    for (int o = 16; o > 0; o >>= 1) s += __shfl_xor_sync(0xffffffffu, s, o);
    if ((tid & 31) == 0) red[tid >> 5] = s;
    __syncthreads();
    if (tid == 0) {
        float t = 0.0f;
#pragma unroll
        for (int w = 0; w < 8; w++) t += red[w];
        float entropy = g_lse_sum - t / (float)N_ROWS;
        float loss = 1000.0f * (1.0f / (float)K_DIM) + 5e-5f * entropy;
        out[out_size - 1] = loss;
    }
}

extern "C" void kernel_launch(void* const* d_in, const int* in_sizes, int n_in,
                              void* d_out, int out_size) {
    const float* in = (const float*)d_in[0];
    const float* cb = (const float*)d_in[1];
    float* out = (float*)d_out;
    (void)in_sizes; (void)n_in;

    const size_t smem = (size_t)(TM * XS_STRIDE + TM * DS_STRIDE + STG_FLOATS) * sizeof(float);
    cudaFuncSetAttribute(k_main, cudaFuncAttributeMaxDynamicSharedMemorySize, (int)smem);

    k_prep<<<K_DIM / 8, 256>>>(cb);
    k_main<<<N_ROWS / TM, NTHR, smem>>>(in, out);
    k_loss<<<1, 256>>>(out, out_size);
}

// round 4
// speedup vs baseline: 2.4401x; 1.0563x over previous
#include <cuda_runtime.h>
#include <cstdint>

#define D_DIM 256
#define K_DIM 1024
#define N_ROWS 32768
#define TM 32
#define NTHR 256
#define XS_STRIDE 260     // mod 32 = 4  -> conflict-free A frags
#define DS_STRIDE 1028    // mod 32 = 4  -> conflict-free A frags / colsum
#define STG_L 1032        // mod 32 = 8  -> conflict-free logits B frags
#define STG_R 264         // mod 32 = 8  -> conflict-free recon  B frags
#define LBUF_FLOATS 8256  // 8 rows  * 1032
#define RBUF_FLOATS 4224  // 16 rows * 264
#define STG_FLOATS (2 * LBUF_FLOATS)   // 16512; recon double-buf (8448) aliases inside

__device__ float g_normC [K_DIM * D_DIM];   // normalized codebook (tf32 bits), [K][D]
__device__ float g_normCT[D_DIM * K_DIM];   // transposed (tf32 bits), [D][K]
__device__ float g_colsum[K_DIM];
__device__ float g_lse_sum;

__device__ __forceinline__ uint32_t f2tf32(float f) {
    uint32_t u;
    asm("cvt.rna.tf32.f32 %0, %1;" : "=r"(u) : "f"(f));
    return u;
}

__device__ __forceinline__ void mma8(float* c, const uint32_t* a, uint32_t b0, uint32_t b1) {
    asm volatile(
        "mma.sync.aligned.m16n8k8.row.col.f32.tf32.tf32.f32 "
        "{%0,%1,%2,%3}, {%4,%5,%6,%7}, {%8,%9}, {%0,%1,%2,%3};"
        : "+f"(c[0]), "+f"(c[1]), "+f"(c[2]), "+f"(c[3])
        : "r"(a[0]), "r"(a[1]), "r"(a[2]), "r"(a[3]), "r"(b0), "r"(b1));
}

__device__ __forceinline__ void cp16(float* dst_smem, const float* src) {
    uint32_t d = (uint32_t)__cvta_generic_to_shared(dst_smem);
    asm volatile("cp.async.cg.shared.global [%0], [%1], 16;" :: "r"(d), "l"(src));
}
#define CP_COMMIT() asm volatile("cp.async.commit_group;")
#define CP_WAIT(N)  asm volatile("cp.async.wait_group %0;" :: "n"(N))

// ---------------------------------------------------------------------------
// Kernel 1: normalize codebook rows -> tf32, write both layouts; zero accums
// ---------------------------------------------------------------------------
__global__ void k_prep(const float* __restrict__ cb) {
    int lane  = threadIdx.x & 31;
    int gwarp = (blockIdx.x * blockDim.x + threadIdx.x) >> 5;
    if (blockIdx.x == 0) {
        for (int k = threadIdx.x; k < K_DIM; k += blockDim.x) g_colsum[k] = 0.0f;
        if (threadIdx.x == 0) g_lse_sum = 0.0f;
    }
    if (gwarp >= K_DIM) return;
    const float* row = cb + (size_t)gwarp * D_DIM;
    float v[8]; float ss = 0.0f;
#pragma unroll
    for (int j = 0; j < 8; j++) { v[j] = row[lane + 32 * j]; ss += v[j] * v[j]; }
#pragma unroll
    for (int o = 16; o > 0; o >>= 1) ss += __shfl_xor_sync(0xffffffffu, ss, o);
    float rinv = rsqrtf(ss);
#pragma unroll
    for (int j = 0; j < 8; j++) {
        int d = lane + 32 * j;
        float nv = __uint_as_float(f2tf32(v[j] * rinv));
        g_normC [gwarp * D_DIM + d] = nv;
        g_normCT[d * K_DIM + gwarp] = nv;
    }
}

// ---------------------------------------------------------------------------
// Kernel 2: fused normalize -> TF32 MMA logits -> softmax+stats -> TF32 MMA recon
// One CTA = 32 rows, 8 warps.  Codebook chunks stream via cp.async into a
// double-buffered staging region, overlapping global latency with MMAs.
// ---------------------------------------------------------------------------
extern __shared__ float s_buf[];

__global__ __launch_bounds__(NTHR, 1) void k_main(const float* __restrict__ in,
                                                  float* __restrict__ out) {
    float* xs  = s_buf;                          // [32][260]
    float* ds  = xs + TM * XS_STRIDE;            // [32][1028]  exp -> distances(tf32)
    float* stg = ds + TM * DS_STRIDE;            // double-buffered staging
    __shared__ float s_rowsum[TM];
    __shared__ float s_inv[TM];
    __shared__ float s_lse;

    const int tid  = threadIdx.x;
    const int warp = tid >> 5, lane = tid & 31;
    const int qr = lane >> 2, qc = lane & 3;     // quad row / col (mma frags)
    const size_t base = (size_t)blockIdx.x * TM * D_DIM;

    if (tid < TM) s_rowsum[tid] = 0.0f;
    if (tid == 0) s_lse = 0.0f;

    // issue logits chunk 0 (rows 0..7 of CT) into LBUF0 — lands during normalize
#pragma unroll
    for (int jj = 0; jj < 8; jj++) {
        int f = jj * NTHR + tid;
        int j = f >> 8, c4 = (f & 255) << 2;
        cp16(stg + j * STG_L + c4, g_normCT + (size_t)j * K_DIM + c4);
    }
    CP_COMMIT();

    for (int i = tid; i < TM * D_DIM; i += NTHR) {
        int r = i >> 8, c = i & 255;
        xs[r * XS_STRIDE + c] = in[base + i];
    }
    __syncthreads();

    // normalize the 32 rows (warp w -> rows 4w..4w+3), round to tf32
#pragma unroll
    for (int rr = 0; rr < 4; rr++) {
        int r = warp * 4 + rr;
        float ss = 0.0f;
#pragma unroll
        for (int j = 0; j < 8; j++) { float t = xs[r * XS_STRIDE + lane + 32 * j]; ss += t * t; }
#pragma unroll
        for (int o = 16; o > 0; o >>= 1) ss += __shfl_xor_sync(0xffffffffu, ss, o);
        float rinv = rsqrtf(ss);
#pragma unroll
        for (int j = 0; j < 8; j++) {
            int idx = r * XS_STRIDE + lane + 32 * j;
            xs[idx] = __uint_as_float(f2tf32(xs[idx] * rinv));
        }
    }
    __syncthreads();

    // ---- logits: L[32,1024] = X[32,256] @ CT[256,1024], warp w owns n [128w,128w+128)
    float acc[2][16][4];
#pragma unroll
    for (int mt = 0; mt < 2; mt++)
#pragma unroll
        for (int nt = 0; nt < 16; nt++)
#pragma unroll
            for (int j = 0; j < 4; j++) acc[mt][nt][j] = 0.0f;

    for (int kd = 0; kd < D_DIM; kd += 8) {
        float* buf = stg + ((kd >> 3) & 1) * LBUF_FLOATS;
        if (kd + 8 < D_DIM) {
            float* nbuf = stg + ((((kd >> 3) & 1) ^ 1)) * LBUF_FLOATS;
#pragma unroll
            for (int jj = 0; jj < 8; jj++) {
                int f = jj * NTHR + tid;
                int j = f >> 8, c4 = (f & 255) << 2;
                cp16(nbuf + j * STG_L + c4, g_normCT + (size_t)(kd + 8 + j) * K_DIM + c4);
            }
            CP_COMMIT();
            CP_WAIT(1);          // chunk kd complete; kd+8 in flight
        } else {
            CP_WAIT(0);
        }
        __syncthreads();

        uint32_t a[2][4];
#pragma unroll
        for (int mt = 0; mt < 2; mt++) {
            const float* xr = xs + (mt * 16 + qr) * XS_STRIDE + kd + qc;
            a[mt][0] = __float_as_uint(xr[0]);
            a[mt][1] = __float_as_uint(xr[8 * XS_STRIDE]);
            a[mt][2] = __float_as_uint(xr[4]);
            a[mt][3] = __float_as_uint(xr[8 * XS_STRIDE + 4]);
        }
#pragma unroll
        for (int nt = 0; nt < 16; nt++) {
            int n0 = warp * 128 + nt * 8 + qr;
            uint32_t b0 = __float_as_uint(buf[qc * STG_L + n0]);
            uint32_t b1 = __float_as_uint(buf[(qc + 4) * STG_L + n0]);
            mma8(acc[0][nt], a[0], b0, b1);
            mma8(acc[1][nt], a[1], b0, b1);
        }
        __syncthreads();
    }

    // issue recon chunk 0 (rows 0..15 of C) into RBUF0 — lands during softmax
#pragma unroll
    for (int jj = 0; jj < 4; jj++) {
        int f = jj * NTHR + tid;
        int j = f >> 6, c4 = (f & 63) << 2;
        cp16(stg + j * STG_R + c4, g_normC + (size_t)j * D_DIM + c4);
    }
    CP_COMMIT();

    // ---- exp (no max needed: logits are cosines in [-1,1]) + row partial sums
    float pr[2][2] = {{0.0f, 0.0f}, {0.0f, 0.0f}};
#pragma unroll
    for (int mt = 0; mt < 2; mt++)
#pragma unroll
        for (int nt = 0; nt < 16; nt++) {
            int col = warp * 128 + nt * 8 + 2 * qc;
            int r0  = mt * 16 + qr;
            float e0 = __expf(acc[mt][nt][0]);
            float e1 = __expf(acc[mt][nt][1]);
            float e2 = __expf(acc[mt][nt][2]);
            float e3 = __expf(acc[mt][nt][3]);
            *reinterpret_cast<float2*>(ds + r0 * DS_STRIDE + col)       = make_float2(e0, e1);
            *reinterpret_cast<float2*>(ds + (r0 + 8) * DS_STRIDE + col) = make_float2(e2, e3);
            pr[mt][0] += e0 + e1;
            pr[mt][1] += e2 + e3;
        }
#pragma unroll
    for (int o = 1; o <= 2; o <<= 1) {
        pr[0][0] += __shfl_xor_sync(0xffffffffu, pr[0][0], o);
        pr[0][1] += __shfl_xor_sync(0xffffffffu, pr[0][1], o);
        pr[1][0] += __shfl_xor_sync(0xffffffffu, pr[1][0], o);
        pr[1][1] += __shfl_xor_sync(0xffffffffu, pr[1][1], o);
    }
    if (qc == 0) {
        atomicAdd(&s_rowsum[qr],      pr[0][0]);
        atomicAdd(&s_rowsum[qr + 8],  pr[0][1]);
        atomicAdd(&s_rowsum[qr + 16], pr[1][0]);
        atomicAdd(&s_rowsum[qr + 24], pr[1][1]);
    }
    __syncthreads();
    if (tid < TM) s_inv[tid] = 1.0f / s_rowsum[tid];
    __syncthreads();

    // ---- normalize -> tf32 distances; Taylor LSE of distances:
    //      sum_k exp(d) = 1024 + sum(d) + t2/2 + t3/6 = 1025 + t2/2 + t3/6
    {
        int r = tid >> 3, seg = tid & 7;
        float inv = s_inv[r];
        float t2 = 0.0f, t3 = 0.0f;
        float* row = ds + r * DS_STRIDE;
#pragma unroll 4
        for (int i = 0; i < 32; i++) {
            float4* p = reinterpret_cast<float4*>(row + ((seg + 8 * i) << 2));
            float4 w = *p;
            w.x = __uint_as_float(f2tf32(w.x * inv));
            w.y = __uint_as_float(f2tf32(w.y * inv));
            w.z = __uint_as_float(f2tf32(w.z * inv));
            w.w = __uint_as_float(f2tf32(w.w * inv));
            *p = w;
            t2 += w.x * w.x + w.y * w.y + w.z * w.z + w.w * w.w;
            t3 += w.x * w.x * w.x + w.y * w.y * w.y + w.z * w.z * w.z + w.w * w.w * w.w;
        }
#pragma unroll
        for (int o = 1; o <= 4; o <<= 1) {
            t2 += __shfl_xor_sync(0xffffffffu, t2, o);
            t3 += __shfl_xor_sync(0xffffffffu, t3, o);
        }
        if (seg == 0)
            atomicAdd(&s_lse, __logf(1025.0f + 0.5f * t2 + 0.16666667f * t3));
    }
    __syncthreads();

    // ---- column sums + lse flush
#pragma unroll
    for (int j = 0; j < 4; j++) {
        int k = tid + j * 256;
        float s = 0.0f;
#pragma unroll
        for (int r = 0; r < TM; r++) s += ds[r * DS_STRIDE + k];
        atomicAdd(&g_colsum[k], s);
    }
    if (tid == 0) atomicAdd(&g_lse_sum, s_lse);

    // ---- recon: R[32,256] = dist[32,1024] @ C[1024,256], warp w owns n [32w,32w+32)
    //      chunks of 16 K-rows, double-buffered via cp.async
    float acc2[2][4][4];
#pragma unroll
    for (int mt = 0; mt < 2; mt++)
#pragma unroll
        for (int nt = 0; nt < 4; nt++)
#pragma unroll
            for (int j = 0; j < 4; j++) acc2[mt][nt][j] = 0.0f;

    for (int k0 = 0; k0 < K_DIM; k0 += 16) {
        float* buf = stg + ((k0 >> 4) & 1) * RBUF_FLOATS;
        if (k0 + 16 < K_DIM) {
            float* nbuf = stg + ((((k0 >> 4) & 1) ^ 1)) * RBUF_FLOATS;
#pragma unroll
            for (int jj = 0; jj < 4; jj++) {
                int f = jj * NTHR + tid;
                int j = f >> 6, c4 = (f & 63) << 2;
                cp16(nbuf + j * STG_R + c4, g_normC + (size_t)(k0 + 16 + j) * D_DIM + c4);
            }
            CP_COMMIT();
            CP_WAIT(1);
        } else {
            CP_WAIT(0);
        }
        __syncthreads();

#pragma unroll
        for (int ks = 0; ks < 2; ks++) {
            int kk = ks * 8;
            uint32_t a[2][4];
#pragma unroll
            for (int mt = 0; mt < 2; mt++) {
                const float* dr = ds + (mt * 16 + qr) * DS_STRIDE + k0 + kk + qc;
                a[mt][0] = __float_as_uint(dr[0]);
                a[mt][1] = __float_as_uint(dr[8 * DS_STRIDE]);
                a[mt][2] = __float_as_uint(dr[4]);
                a[mt][3] = __float_as_uint(dr[8 * DS_STRIDE + 4]);
            }
#pragma unroll
            for (int nt = 0; nt < 4; nt++) {
                int n0 = warp * 32 + nt * 8 + qr;
                uint32_t b0 = __float_as_uint(buf[(kk + qc) * STG_R + n0]);
                uint32_t b1 = __float_as_uint(buf[(kk + qc + 4) * STG_R + n0]);
                mma8(acc2[0][nt], a[0], b0, b1);
                mma8(acc2[1][nt], a[1], b0, b1);
            }
        }
        __syncthreads();
    }

    // ---- write reconstruction
#pragma unroll
    for (int mt = 0; mt < 2; mt++)
#pragma unroll
        for (int nt = 0; nt < 4; nt++) {
            int r0  = mt * 16 + qr;
            int col = warp * 32 + nt * 8 + 2 * qc;
            *reinterpret_cast<float2*>(out + base + (size_t)r0 * D_DIM + col) =
                make_float2(acc2[mt][nt][0], acc2[mt][nt][1]);
            *reinterpret_cast<float2*>(out + base + (size_t)(r0 + 8) * D_DIM + col) =
                make_float2(acc2[mt][nt][2], acc2[mt][nt][3]);
        }
}

// ---------------------------------------------------------------------------
// Kernel 3: finalize loss.  l1 == 1/K exactly.
// entropy = sum_i lse_i - ||colsum||^2 / N
// ---------------------------------------------------------------------------
__global__ void k_loss(float* __restrict__ out, int out_size) {
    __shared__ float red[8];
    int tid = threadIdx.x;
    float s = 0.0f;
    for (int k = tid; k < K_DIM; k += 256) { float c = g_colsum[k]; s += c * c; }
#pragma unroll
    for (int o = 16; o > 0; o >>= 1) s += __shfl_xor_sync(0xffffffffu, s, o);
    if ((tid & 31) == 0) red[tid >> 5] = s;
    __syncthreads();
    if (tid == 0) {
        float t = 0.0f;
#pragma unroll
        for (int w = 0; w < 8; w++) t += red[w];
        float entropy = g_lse_sum - t / (float)N_ROWS;
        float loss = 1000.0f * (1.0f / (float)K_DIM) + 5e-5f * entropy;
        out[out_size - 1] = loss;
    }
}

extern "C" void kernel_launch(void* const* d_in, const int* in_sizes, int n_in,
                              void* d_out, int out_size) {
    const float* in = (const float*)d_in[0];
    const float* cb = (const float*)d_in[1];
    float* out = (float*)d_out;
    (void)in_sizes; (void)n_in;

    const size_t smem = (size_t)(TM * XS_STRIDE + TM * DS_STRIDE + STG_FLOATS) * sizeof(float);
    cudaFuncSetAttribute(k_main, cudaFuncAttributeMaxDynamicSharedMemorySize, (int)smem);

    k_prep<<<K_DIM / 8, 256>>>(cb);
    k_main<<<N_ROWS / TM, NTHR, smem>>>(in, out);
    k_loss<<<1, 256>>>(out, out_size);
}

// round 5
// speedup vs baseline: 3.8424x; 1.5747x over previous
#include <cuda_runtime.h>
#include <cuda_fp16.h>
#include <cstdint>

#define D_DIM 256
#define K_DIM 1024
#define N_ROWS 32768
#define TM 32
#define NTHR 256

// strides in HALFS
#define XS_STRIDE 264      // 132 words, mod32=4 -> conflict-free A frags
#define DS_STRIDE 1032     // 516 words, mod32=4 -> conflict-free A frags / half2 stores
#define STG_L 24           // 12 words,  mod32: qr*12+qc all-distinct -> conflict-free B frags
#define STG_R 40           // 20 words,  qr*20+qc all-distinct       -> conflict-free B frags
#define LBUF_HALFS (1024 * STG_L)   // 24576 halfs = 49152 B
#define RBUF_HALFS (256 * STG_R)    // 10240 halfs = 20480 B

// codebook pre-chunked for cp.async streaming (written by k_prep)
__device__ __half g_chunksL[16 * 1024 * 16];  // [d-chunk][n=1024][16 d]   (logits B)
__device__ __half g_chunksR[32 * 256 * 32];   // [k-chunk][n=256 d][32 k]  (recon  B)
__device__ float  g_colsum[K_DIM];
__device__ float  g_lse_sum;

__device__ __forceinline__ void mma16(float* c, const uint32_t* a, uint32_t b0, uint32_t b1) {
    asm volatile(
        "mma.sync.aligned.m16n8k16.row.col.f32.f16.f16.f32 "
        "{%0,%1,%2,%3}, {%4,%5,%6,%7}, {%8,%9}, {%0,%1,%2,%3};"
        : "+f"(c[0]), "+f"(c[1]), "+f"(c[2]), "+f"(c[3])
        : "r"(a[0]), "r"(a[1]), "r"(a[2]), "r"(a[3]), "r"(b0), "r"(b1));
}

__device__ __forceinline__ void cp16(__half* dst_smem, const __half* src) {
    uint32_t d = (uint32_t)__cvta_generic_to_shared(dst_smem);
    asm volatile("cp.async.cg.shared.global [%0], [%1], 16;" :: "r"(d), "l"(src));
}
#define CP_COMMIT() asm volatile("cp.async.commit_group;")
#define CP_WAIT(N)  asm volatile("cp.async.wait_group %0;" :: "n"(N))

// ---------------------------------------------------------------------------
// Kernel 1: normalize codebook rows -> fp16, write both chunked layouts
// ---------------------------------------------------------------------------
__global__ void k_prep(const float* __restrict__ cb) {
    int lane  = threadIdx.x & 31;
    int gwarp = (blockIdx.x * blockDim.x + threadIdx.x) >> 5;
    if (blockIdx.x == 0) {
        for (int k = threadIdx.x; k < K_DIM; k += blockDim.x) g_colsum[k] = 0.0f;
        if (threadIdx.x == 0) g_lse_sum = 0.0f;
    }
    if (gwarp >= K_DIM) return;
    const int k = gwarp;
    const float* row = cb + (size_t)k * D_DIM;
    float v[8]; float ss = 0.0f;
#pragma unroll
    for (int j = 0; j < 8; j++) { v[j] = row[lane + 32 * j]; ss += v[j] * v[j]; }
#pragma unroll
    for (int o = 16; o > 0; o >>= 1) ss += __shfl_xor_sync(0xffffffffu, ss, o);
    float rinv = rsqrtf(ss);
#pragma unroll
    for (int j = 0; j < 8; j++) {
        int d = lane + 32 * j;
        __half h = __float2half_rn(v[j] * rinv);
        g_chunksL[(d >> 4) * (1024 * 16) + k * 16 + (d & 15)] = h;   // [dchunk][k][d%16]
        g_chunksR[(k >> 5) * (256 * 32) + d * 32 + (k & 31)]  = h;   // [kchunk][d][k%32]
    }
}

// ---------------------------------------------------------------------------
// Kernel 2: fused normalize -> fp16 MMA logits -> fused softmax/stats -> fp16 MMA recon
// One CTA = 32 rows, 8 warps. cp.async double-buffered codebook streaming.
// ---------------------------------------------------------------------------
extern __shared__ __half s_hbuf[];

__global__ __launch_bounds__(NTHR, 1) void k_main(const float* __restrict__ in,
                                                  float* __restrict__ out) {
    __half* xs  = s_hbuf;                        // [32][264] halfs (normalized inputs)
    __half* ds  = xs + TM * XS_STRIDE;           // [32][1032] halfs (distances)
    __half* stg = ds + TM * DS_STRIDE;           // staging, double-buffered
    __shared__ float s_rowsum[TM];
    __shared__ float s_inv[TM];
    __shared__ float s_t2[TM];
    __shared__ float s_t3[TM];

    const int tid  = threadIdx.x;
    const int warp = tid >> 5, lane = tid & 31;
    const int qr = lane >> 2, qc = lane & 3;
    const size_t base = (size_t)blockIdx.x * TM * D_DIM;

    if (tid < TM) { s_rowsum[tid] = 0.0f; s_t2[tid] = 0.0f; s_t3[tid] = 0.0f; }

    // issue logits chunk 0 -> LBUF0 (lands during input load/normalize)
#pragma unroll
    for (int jj = 0; jj < 8; jj++) {
        int f = jj * NTHR + tid;
        int n = f >> 1, sel = (f & 1) << 3;  // 0 or 8 halfs
        cp16(stg + n * STG_L + sel, g_chunksL + n * 16 + sel);
    }
    CP_COMMIT();

    // load + normalize input rows (warp w -> rows 4w..4w+3) -> fp16 in xs
#pragma unroll
    for (int rr = 0; rr < 4; rr++) {
        int r = warp * 4 + rr;
        const float* rp = in + base + (size_t)r * D_DIM;
        float v[8]; float ss = 0.0f;
#pragma unroll
        for (int j = 0; j < 8; j++) { v[j] = rp[lane + 32 * j]; ss += v[j] * v[j]; }
#pragma unroll
        for (int o = 16; o > 0; o >>= 1) ss += __shfl_xor_sync(0xffffffffu, ss, o);
        float rinv = rsqrtf(ss);
#pragma unroll
        for (int j = 0; j < 8; j++)
            xs[r * XS_STRIDE + lane + 32 * j] = __float2half_rn(v[j] * rinv);
    }
    __syncthreads();

    // ---- logits: L[32,1024] = X @ CT, 16 chunks of 16 d.  warp w: n in [128w,128w+128)
    float acc[2][16][4];
#pragma unroll
    for (int mt = 0; mt < 2; mt++)
#pragma unroll
        for (int nt = 0; nt < 16; nt++)
#pragma unroll
            for (int j = 0; j < 4; j++) acc[mt][nt][j] = 0.0f;

    for (int c = 0; c < 16; c++) {
        __half* buf = stg + (c & 1) * LBUF_HALFS;
        if (c + 1 < 16) {
            __half* nbuf = stg + ((c & 1) ^ 1) * LBUF_HALFS;
            const __half* src = g_chunksL + (size_t)(c + 1) * (1024 * 16);
#pragma unroll
            for (int jj = 0; jj < 8; jj++) {
                int f = jj * NTHR + tid;
                int n = f >> 1, sel = (f & 1) << 3;
                cp16(nbuf + n * STG_L + sel, src + n * 16 + sel);
            }
            CP_COMMIT();
            CP_WAIT(1);
        } else {
            CP_WAIT(0);
        }
        __syncthreads();

        uint32_t a[2][4];
#pragma unroll
        for (int mt = 0; mt < 2; mt++) {
            const __half* xr = xs + (mt * 16 + qr) * XS_STRIDE + c * 16 + 2 * qc;
            a[mt][0] = *reinterpret_cast<const uint32_t*>(xr);
            a[mt][1] = *reinterpret_cast<const uint32_t*>(xr + 8 * XS_STRIDE);
            a[mt][2] = *reinterpret_cast<const uint32_t*>(xr + 8);
            a[mt][3] = *reinterpret_cast<const uint32_t*>(xr + 8 * XS_STRIDE + 8);
        }
#pragma unroll
        for (int nt = 0; nt < 16; nt++) {
            int n0 = warp * 128 + nt * 8 + qr;
            const __half* bp = buf + n0 * STG_L + 2 * qc;
            uint32_t b0 = *reinterpret_cast<const uint32_t*>(bp);
            uint32_t b1 = *reinterpret_cast<const uint32_t*>(bp + 8);
            mma16(acc[0][nt], a[0], b0, b1);
            mma16(acc[1][nt], a[1], b0, b1);
        }
        __syncthreads();
    }

    // issue recon chunk 0 -> RBUF0 (lands during softmax phase)
#pragma unroll
    for (int jj = 0; jj < 4; jj++) {
        int f = jj * NTHR + tid;
        int n = f >> 2, sel = (f & 3) << 3;
        cp16(stg + n * STG_R + sel, g_chunksR + n * 32 + sel);
    }
    CP_COMMIT();

    // ---- exp in registers (logits are cosines in [-1,1]: no max pass) + row sums
    float pr[4] = {0.0f, 0.0f, 0.0f, 0.0f};   // rows qr, qr+8, qr+16, qr+24
#pragma unroll
    for (int mt = 0; mt < 2; mt++)
#pragma unroll
        for (int nt = 0; nt < 16; nt++) {
            float e0 = __expf(acc[mt][nt][0]);
            float e1 = __expf(acc[mt][nt][1]);
            float e2 = __expf(acc[mt][nt][2]);
            float e3 = __expf(acc[mt][nt][3]);
            acc[mt][nt][0] = e0; acc[mt][nt][1] = e1;
            acc[mt][nt][2] = e2; acc[mt][nt][3] = e3;
            pr[2 * mt]     += e0 + e1;
            pr[2 * mt + 1] += e2 + e3;
        }
#pragma unroll
    for (int o = 1; o <= 2; o <<= 1)
#pragma unroll
        for (int p = 0; p < 4; p++) pr[p] += __shfl_xor_sync(0xffffffffu, pr[p], o);
    if (qc == 0) {
        atomicAdd(&s_rowsum[qr],      pr[0]);
        atomicAdd(&s_rowsum[qr + 8],  pr[1]);
        atomicAdd(&s_rowsum[qr + 16], pr[2]);
        atomicAdd(&s_rowsum[qr + 24], pr[3]);
    }
    __syncthreads();
    if (tid < TM) s_inv[tid] = 1.0f / s_rowsum[tid];
    __syncthreads();

    // ---- fused: rescale (single fp16 round) -> ds; colsum; Taylor t2/t3
    {
        float iv0 = s_inv[qr], iv1 = s_inv[qr + 8], iv2 = s_inv[qr + 16], iv3 = s_inv[qr + 24];
        float t2[4] = {0, 0, 0, 0}, t3[4] = {0, 0, 0, 0};
#pragma unroll
        for (int nt = 0; nt < 16; nt++) {
            int col = warp * 128 + nt * 8 + 2 * qc;
            float cp0 = 0.0f, cp1 = 0.0f;   // column partials over this thread's 4 rows
#pragma unroll
            for (int mt = 0; mt < 2; mt++) {
                float ivA = (mt == 0) ? iv0 : iv2;
                float ivB = (mt == 0) ? iv1 : iv3;
                float d0 = acc[mt][nt][0] * ivA;
                float d1 = acc[mt][nt][1] * ivA;
                float d2 = acc[mt][nt][2] * ivB;
                float d3 = acc[mt][nt][3] * ivB;
                int r0 = mt * 16 + qr;
                *reinterpret_cast<__half2*>(ds + r0 * DS_STRIDE + col)       = __floats2half2_rn(d0, d1);
                *reinterpret_cast<__half2*>(ds + (r0 + 8) * DS_STRIDE + col) = __floats2half2_rn(d2, d3);
                t2[2 * mt]     += d0 * d0 + d1 * d1;
                t3[2 * mt]     += d0 * d0 * d0 + d1 * d1 * d1;
                t2[2 * mt + 1] += d2 * d2 + d3 * d3;
                t3[2 * mt + 1] += d2 * d2 * d2 + d3 * d3 * d3;
                cp0 += d0 + d2;
                cp1 += d1 + d3;
            }
            // reduce over qr lanes (lane bits 2..4) -> full column sum in lanes 0..3
#pragma unroll
            for (int o = 4; o <= 16; o <<= 1) {
                cp0 += __shfl_xor_sync(0xffffffffu, cp0, o);
                cp1 += __shfl_xor_sync(0xffffffffu, cp1, o);
            }
            if (qr == 0) {
                atomicAdd(&g_colsum[col],     cp0);
                atomicAdd(&g_colsum[col + 1], cp1);
            }
        }
        // reduce t2/t3 over qc lanes
#pragma unroll
        for (int o = 1; o <= 2; o <<= 1)
#pragma unroll
            for (int p = 0; p < 4; p++) {
                t2[p] += __shfl_xor_sync(0xffffffffu, t2[p], o);
                t3[p] += __shfl_xor_sync(0xffffffffu, t3[p], o);
            }
        if (qc == 0) {
#pragma unroll
            for (int p = 0; p < 4; p++) {
                atomicAdd(&s_t2[qr + 8 * p], t2[p]);
                atomicAdd(&s_t3[qr + 8 * p], t3[p]);
            }
        }
    }
    __syncthreads();

    // per-row lse = log(sum_k exp(d)) = log(1025 + t2/2 + t3/6); one flush per CTA
    if (tid < TM) {
        float l = __logf(1025.0f + 0.5f * s_t2[tid] + 0.16666667f * s_t3[tid]);
#pragma unroll
        for (int o = 16; o > 0; o >>= 1) l += __shfl_xor_sync(0xffffffffu, l, o);
        if (tid == 0) atomicAdd(&g_lse_sum, l);
    }

    // ---- recon: R[32,256] = dist[32,1024] @ C, 32 chunks of 32 k.  warp w: n in [32w,32w+32)
    float acc2[2][4][4];
#pragma unroll
    for (int mt = 0; mt < 2; mt++)
#pragma unroll
        for (int nt = 0; nt < 4; nt++)
#pragma unroll
            for (int j = 0; j < 4; j++) acc2[mt][nt][j] = 0.0f;

    for (int c = 0; c < 32; c++) {
        __half* buf = stg + (c & 1) * RBUF_HALFS;
        if (c + 1 < 32) {
            __half* nbuf = stg + ((c & 1) ^ 1) * RBUF_HALFS;
            const __half* src = g_chunksR + (size_t)(c + 1) * (256 * 32);
#pragma unroll
            for (int jj = 0; jj < 4; jj++) {
                int f = jj * NTHR + tid;
                int n = f >> 2, sel = (f & 3) << 3;
                cp16(nbuf + n * STG_R + sel, src + n * 32 + sel);
            }
            CP_COMMIT();
            CP_WAIT(1);
        } else {
            CP_WAIT(0);
        }
        __syncthreads();

#pragma unroll
        for (int ks = 0; ks < 2; ks++) {
            uint32_t a[2][4];
#pragma unroll
            for (int mt = 0; mt < 2; mt++) {
                const __half* dr = ds + (mt * 16 + qr) * DS_STRIDE + c * 32 + ks * 16 + 2 * qc;
                a[mt][0] = *reinterpret_cast<const uint32_t*>(dr);
                a[mt][1] = *reinterpret_cast<const uint32_t*>(dr + 8 * DS_STRIDE);
                a[mt][2] = *reinterpret_cast<const uint32_t*>(dr + 8);
                a[mt][3] = *reinterpret_cast<const uint32_t*>(dr + 8 * DS_STRIDE + 8);
            }
#pragma unroll
            for (int nt = 0; nt < 4; nt++) {
                int n0 = warp * 32 + nt * 8 + qr;
                const __half* bp = buf + n0 * STG_R + ks * 16 + 2 * qc;
                uint32_t b0 = *reinterpret_cast<const uint32_t*>(bp);
                uint32_t b1 = *reinterpret_cast<const uint32_t*>(bp + 8);
                mma16(acc2[0][nt], a[0], b0, b1);
                mma16(acc2[1][nt], a[1], b0, b1);
            }
        }
        __syncthreads();
    }

    // ---- write reconstruction
#pragma unroll
    for (int mt = 0; mt < 2; mt++)
#pragma unroll
        for (int nt = 0; nt < 4; nt++) {
            int r0  = mt * 16 + qr;
            int col = warp * 32 + nt * 8 + 2 * qc;
            *reinterpret_cast<float2*>(out + base + (size_t)r0 * D_DIM + col) =
                make_float2(acc2[mt][nt][0], acc2[mt][nt][1]);
            *reinterpret_cast<float2*>(out + base + (size_t)(r0 + 8) * D_DIM + col) =
                make_float2(acc2[mt][nt][2], acc2[mt][nt][3]);
        }
}

// ---------------------------------------------------------------------------
// Kernel 3: finalize loss.  l1 == 1/K exactly.
// entropy = sum_i lse_i - ||colsum||^2 / N
// ---------------------------------------------------------------------------
__global__ void k_loss(float* __restrict__ out, int out_size) {
    __shared__ float red[8];
    int tid = threadIdx.x;
    float s = 0.0f;
    for (int k = tid; k < K_DIM; k += 256) { float c = g_colsum[k]; s += c * c; }
#pragma unroll
    for (int o = 16; o > 0; o >>= 1) s += __shfl_xor_sync(0xffffffffu, s, o);
    if ((tid & 31) == 0) red[tid >> 5] = s;
    __syncthreads();
    if (tid == 0) {
        float t = 0.0f;
#pragma unroll
        for (int w = 0; w < 8; w++) t += red[w];
        float entropy = g_lse_sum - t / (float)N_ROWS;
        float loss = 1000.0f * (1.0f / (float)K_DIM) + 5e-5f * entropy;
        out[out_size - 1] = loss;
    }
}

extern "C" void kernel_launch(void* const* d_in, const int* in_sizes, int n_in,
                              void* d_out, int out_size) {
    const float* in = (const float*)d_in[0];
    const float* cb = (const float*)d_in[1];
    float* out = (float*)d_out;
    (void)in_sizes; (void)n_in;

    const size_t smem = (size_t)(TM * XS_STRIDE + TM * DS_STRIDE + 2 * LBUF_HALFS) * sizeof(__half);
    cudaFuncSetAttribute(k_main, cudaFuncAttributeMaxDynamicSharedMemorySize, (int)smem);

    k_prep<<<K_DIM / 8, 256>>>(cb);
    k_main<<<N_ROWS / TM, NTHR, smem>>>(in, out);
    k_loss<<<1, 256>>>(out, out_size);
}

// round 6
// speedup vs baseline: 5.4446x; 1.4170x over previous
#include <cuda_runtime.h>
#include <cuda_fp16.h>
#include <cstdint>

#define D_DIM 256
#define K_DIM 1024
#define N_ROWS 32768
#define TM 32
#define NTHR 256

// strides in HALFS
#define XS_STRIDE 264          // conflict-free A frags (inputs)
#define DS_STRIDE 1032         // conflict-free A frags / half2 stores (distances)
#define STG_L 16               // unpadded: contiguous bulk-copy chunks (2-way B conflict, accepted)
#define STG_R 32               // unpadded (4-way B conflict, accepted)
#define LBUF_HALFS (1024 * STG_L)   // 16384 halfs = 32 KB
#define RBUF_HALFS (256 * STG_R)    // 8192 halfs  = 16 KB
#define LBUF_BYTES (LBUF_HALFS * 2)
#define RBUF_BYTES (RBUF_HALFS * 2)

// codebook pre-chunked for bulk-async streaming (written by k_prep)
__device__ __align__(16) __half g_chunksL[16 * 1024 * 16];  // [d-chunk][n=1024][16 d]
__device__ __align__(16) __half g_chunksR[32 * 256 * 32];   // [k-chunk][d=256][32 k]
__device__ float g_colsum[K_DIM];
__device__ float g_lse_sum;

__device__ __forceinline__ void mma16(float* c, const uint32_t* a, uint32_t b0, uint32_t b1) {
    asm volatile(
        "mma.sync.aligned.m16n8k16.row.col.f32.f16.f16.f32 "
        "{%0,%1,%2,%3}, {%4,%5,%6,%7}, {%8,%9}, {%0,%1,%2,%3};"
        : "+f"(c[0]), "+f"(c[1]), "+f"(c[2]), "+f"(c[3])
        : "r"(a[0]), "r"(a[1]), "r"(a[2]), "r"(a[3]), "r"(b0), "r"(b1));
}

__device__ __forceinline__ void bulk_cp(uint32_t dst_smem, const void* src,
                                        uint32_t bytes, uint32_t mbar) {
    asm volatile(
        "cp.async.bulk.shared::cta.global.mbarrier::complete_tx::bytes [%0], [%1], %2, [%3];"
        :: "r"(dst_smem), "l"(src), "r"(bytes), "r"(mbar) : "memory");
}
__device__ __forceinline__ void mbar_init(uint32_t mbar, uint32_t cnt) {
    asm volatile("mbarrier.init.shared.b64 [%0], %1;" :: "r"(mbar), "r"(cnt) : "memory");
}
__device__ __forceinline__ void mbar_expect(uint32_t mbar, uint32_t bytes) {
    asm volatile("mbarrier.arrive.expect_tx.shared.b64 _, [%0], %1;"
                 :: "r"(mbar), "r"(bytes) : "memory");
}
__device__ __forceinline__ void mbar_wait(uint32_t mbar, uint32_t parity) {
    asm volatile(
        "{\n\t.reg .pred P;\n\t"
        "WAIT_%=:\n\t"
        "mbarrier.try_wait.parity.acquire.cta.shared::cta.b64 P, [%0], %1, 0x989680;\n\t"
        "@P bra.uni DONE_%=;\n\t"
        "bra.uni WAIT_%=;\n\t"
        "DONE_%=:\n\t}"
        :: "r"(mbar), "r"(parity) : "memory");
}

// ---------------------------------------------------------------------------
// Kernel 1: normalize codebook rows -> fp16, write both chunked layouts
// ---------------------------------------------------------------------------
__global__ void k_prep(const float* __restrict__ cb) {
    int lane  = threadIdx.x & 31;
    int gwarp = (blockIdx.x * blockDim.x + threadIdx.x) >> 5;
    if (blockIdx.x == 0) {
        for (int k = threadIdx.x; k < K_DIM; k += blockDim.x) g_colsum[k] = 0.0f;
        if (threadIdx.x == 0) g_lse_sum = 0.0f;
    }
    if (gwarp >= K_DIM) return;
    const int k = gwarp;
    const float* row = cb + (size_t)k * D_DIM;
    float v[8]; float ss = 0.0f;
#pragma unroll
    for (int j = 0; j < 8; j++) { v[j] = row[lane + 32 * j]; ss += v[j] * v[j]; }
#pragma unroll
    for (int o = 16; o > 0; o >>= 1) ss += __shfl_xor_sync(0xffffffffu, ss, o);
    float rinv = rsqrtf(ss);
#pragma unroll
    for (int j = 0; j < 8; j++) {
        int d = lane + 32 * j;
        __half h = __float2half_rn(v[j] * rinv);
        g_chunksL[(d >> 4) * (1024 * 16) + k * 16 + (d & 15)] = h;   // [dchunk][k][d%16]
        g_chunksR[(k >> 5) * (256 * 32) + d * 32 + (k & 31)]  = h;   // [kchunk][d][k%32]
    }
}

// ---------------------------------------------------------------------------
// Kernel 2: fused normalize -> fp16 MMA logits -> fused softmax/stats -> fp16 MMA recon
// One CTA = 32 rows, 8 warps.  Codebook streams via cp.async.bulk (1 instr per
// 16-32KB chunk) into double-buffered SMEM, completion via mbarrier.
// ---------------------------------------------------------------------------
extern __shared__ __half s_hbuf[];

__global__ __launch_bounds__(NTHR, 1) void k_main(const float* __restrict__ in,
                                                  float* __restrict__ out) {
    __half* xs  = s_hbuf;                        // [32][264] halfs (normalized inputs)
    __half* ds  = xs + TM * XS_STRIDE;           // [32][1032] halfs (distances)
    __half* stg = ds + TM * DS_STRIDE;           // double-buffered staging (2 x 32 KB)
    __shared__ __align__(8) unsigned long long s_mbar[2];
    __shared__ float s_rowsum[TM];
    __shared__ float s_inv[TM];
    __shared__ float s_t2[TM];
    __shared__ float s_t3[TM];

    const int tid  = threadIdx.x;
    const int warp = tid >> 5, lane = tid & 31;
    const int qr = lane >> 2, qc = lane & 3;
    const size_t base = (size_t)blockIdx.x * TM * D_DIM;

    const uint32_t stg_u32 = (uint32_t)__cvta_generic_to_shared(stg);
    const uint32_t mb0 = (uint32_t)__cvta_generic_to_shared(&s_mbar[0]);
    const uint32_t mb1 = (uint32_t)__cvta_generic_to_shared(&s_mbar[1]);

    if (tid < TM) { s_rowsum[tid] = 0.0f; s_t2[tid] = 0.0f; s_t3[tid] = 0.0f; }
    if (tid == 0) {
        mbar_init(mb0, 1);
        mbar_init(mb1, 1);
        asm volatile("fence.proxy.async.shared::cta;" ::: "memory");
    }
    __syncthreads();

    // issue logits chunk 0 -> buf0 (lands during input load/normalize)
    if (tid == 0) {
        mbar_expect(mb0, LBUF_BYTES);
        bulk_cp(stg_u32, g_chunksL, LBUF_BYTES, mb0);
    }

    // load + normalize input rows (warp w -> rows 4w..4w+3) -> fp16 in xs
#pragma unroll
    for (int rr = 0; rr < 4; rr++) {
        int r = warp * 4 + rr;
        const float* rp = in + base + (size_t)r * D_DIM;
        float v[8]; float ss = 0.0f;
#pragma unroll
        for (int j = 0; j < 8; j++) { v[j] = rp[lane + 32 * j]; ss += v[j] * v[j]; }
#pragma unroll
        for (int o = 16; o > 0; o >>= 1) ss += __shfl_xor_sync(0xffffffffu, ss, o);
        float rinv = rsqrtf(ss);
#pragma unroll
        for (int j = 0; j < 8; j++)
            xs[r * XS_STRIDE + lane + 32 * j] = __float2half_rn(v[j] * rinv);
    }
    __syncthreads();

    // ---- logits: L[32,1024] = X @ CT, 16 chunks of 16 d.  warp w: n in [128w,128w+128)
    float acc[2][16][4];
#pragma unroll
    for (int mt = 0; mt < 2; mt++)
#pragma unroll
        for (int nt = 0; nt < 16; nt++)
#pragma unroll
            for (int j = 0; j < 4; j++) acc[mt][nt][j] = 0.0f;

    for (int c = 0; c < 16; c++) {
        __half* buf = stg + (c & 1) * LBUF_HALFS;
        if (tid == 0 && c + 1 < 16) {
            uint32_t b = (c + 1) & 1;
            uint32_t mb = b ? mb1 : mb0;
            mbar_expect(mb, LBUF_BYTES);
            bulk_cp(stg_u32 + b * LBUF_BYTES,
                    g_chunksL + (size_t)(c + 1) * LBUF_HALFS, LBUF_BYTES, mb);
        }
        mbar_wait((c & 1) ? mb1 : mb0, (c >> 1) & 1);

        uint32_t a[2][4];
#pragma unroll
        for (int mt = 0; mt < 2; mt++) {
            const __half* xr = xs + (mt * 16 + qr) * XS_STRIDE + c * 16 + 2 * qc;
            a[mt][0] = *reinterpret_cast<const uint32_t*>(xr);
            a[mt][1] = *reinterpret_cast<const uint32_t*>(xr + 8 * XS_STRIDE);
            a[mt][2] = *reinterpret_cast<const uint32_t*>(xr + 8);
            a[mt][3] = *reinterpret_cast<const uint32_t*>(xr + 8 * XS_STRIDE + 8);
        }
#pragma unroll
        for (int nt = 0; nt < 16; nt++) {
            int n0 = warp * 128 + nt * 8 + qr;
            const __half* bp = buf + n0 * STG_L + 2 * qc;
            uint32_t b0 = *reinterpret_cast<const uint32_t*>(bp);
            uint32_t b1 = *reinterpret_cast<const uint32_t*>(bp + 8);
            mma16(acc[0][nt], a[0], b0, b1);
            mma16(acc[1][nt], a[1], b0, b1);
        }
        __syncthreads();
    }

    // issue recon chunk 0 -> buf0 (lands during softmax phase); parities reset to 0
    if (tid == 0) {
        mbar_expect(mb0, RBUF_BYTES);
        bulk_cp(stg_u32, g_chunksR, RBUF_BYTES, mb0);
    }

    // ---- exp in registers (logits are cosines in [-1,1]: no max pass) + row sums
    float pr[4] = {0.0f, 0.0f, 0.0f, 0.0f};
#pragma unroll
    for (int mt = 0; mt < 2; mt++)
#pragma unroll
        for (int nt = 0; nt < 16; nt++) {
            float e0 = __expf(acc[mt][nt][0]);
            float e1 = __expf(acc[mt][nt][1]);
            float e2 = __expf(acc[mt][nt][2]);
            float e3 = __expf(acc[mt][nt][3]);
            acc[mt][nt][0] = e0; acc[mt][nt][1] = e1;
            acc[mt][nt][2] = e2; acc[mt][nt][3] = e3;
            pr[2 * mt]     += e0 + e1;
            pr[2 * mt + 1] += e2 + e3;
        }
#pragma unroll
    for (int o = 1; o <= 2; o <<= 1)
#pragma unroll
        for (int p = 0; p < 4; p++) pr[p] += __shfl_xor_sync(0xffffffffu, pr[p], o);
    if (qc == 0) {
        atomicAdd(&s_rowsum[qr],      pr[0]);
        atomicAdd(&s_rowsum[qr + 8],  pr[1]);
        atomicAdd(&s_rowsum[qr + 16], pr[2]);
        atomicAdd(&s_rowsum[qr + 24], pr[3]);
    }
    __syncthreads();
    if (tid < TM) s_inv[tid] = 1.0f / s_rowsum[tid];
    __syncthreads();

    // ---- fused: rescale (single fp16 round) -> ds; colsum; Taylor t2/t3
    {
        float iv0 = s_inv[qr], iv1 = s_inv[qr + 8], iv2 = s_inv[qr + 16], iv3 = s_inv[qr + 24];
        float t2[4] = {0, 0, 0, 0}, t3[4] = {0, 0, 0, 0};
#pragma unroll
        for (int nt = 0; nt < 16; nt++) {
            int col = warp * 128 + nt * 8 + 2 * qc;
            float cp0 = 0.0f, cp1 = 0.0f;
#pragma unroll
            for (int mt = 0; mt < 2; mt++) {
                float ivA = (mt == 0) ? iv0 : iv2;
                float ivB = (mt == 0) ? iv1 : iv3;
                float d0 = acc[mt][nt][0] * ivA;
                float d1 = acc[mt][nt][1] * ivA;
                float d2 = acc[mt][nt][2] * ivB;
                float d3 = acc[mt][nt][3] * ivB;
                int r0 = mt * 16 + qr;
                *reinterpret_cast<__half2*>(ds + r0 * DS_STRIDE + col)       = __floats2half2_rn(d0, d1);
                *reinterpret_cast<__half2*>(ds + (r0 + 8) * DS_STRIDE + col) = __floats2half2_rn(d2, d3);
                t2[2 * mt]     += d0 * d0 + d1 * d1;
                t3[2 * mt]     += d0 * d0 * d0 + d1 * d1 * d1;
                t2[2 * mt + 1] += d2 * d2 + d3 * d3;
                t3[2 * mt + 1] += d2 * d2 * d2 + d3 * d3 * d3;
                cp0 += d0 + d2;
                cp1 += d1 + d3;
            }
#pragma unroll
            for (int o = 4; o <= 16; o <<= 1) {
                cp0 += __shfl_xor_sync(0xffffffffu, cp0, o);
                cp1 += __shfl_xor_sync(0xffffffffu, cp1, o);
            }
            if (qr == 0) {
                atomicAdd(&g_colsum[col],     cp0);
                atomicAdd(&g_colsum[col + 1], cp1);
            }
        }
#pragma unroll
        for (int o = 1; o <= 2; o <<= 1)
#pragma unroll
            for (int p = 0; p < 4; p++) {
                t2[p] += __shfl_xor_sync(0xffffffffu, t2[p], o);
                t3[p] += __shfl_xor_sync(0xffffffffu, t3[p], o);
            }
        if (qc == 0) {
#pragma unroll
            for (int p = 0; p < 4; p++) {
                atomicAdd(&s_t2[qr + 8 * p], t2[p]);
                atomicAdd(&s_t3[qr + 8 * p], t3[p]);
            }
        }
    }
    __syncthreads();

    // per-row lse = log(1025 + t2/2 + t3/6); one flush per CTA
    if (tid < TM) {
        float l = __logf(1025.0f + 0.5f * s_t2[tid] + 0.16666667f * s_t3[tid]);
#pragma unroll
        for (int o = 16; o > 0; o >>= 1) l += __shfl_xor_sync(0xffffffffu, l, o);
        if (tid == 0) atomicAdd(&g_lse_sum, l);
    }

    // ---- recon: R[32,256] = dist[32,1024] @ C, 32 chunks of 32 k.  warp w: n in [32w,32w+32)
    float acc2[2][4][4];
#pragma unroll
    for (int mt = 0; mt < 2; mt++)
#pragma unroll
        for (int nt = 0; nt < 4; nt++)
#pragma unroll
            for (int j = 0; j < 4; j++) acc2[mt][nt][j] = 0.0f;

    for (int c = 0; c < 32; c++) {
        __half* buf = stg + (c & 1) * RBUF_HALFS;
        if (tid == 0 && c + 1 < 32) {
            uint32_t b = (c + 1) & 1;
            uint32_t mb = b ? mb1 : mb0;
            mbar_expect(mb, RBUF_BYTES);
            bulk_cp(stg_u32 + b * RBUF_BYTES,
                    g_chunksR + (size_t)(c + 1) * RBUF_HALFS, RBUF_BYTES, mb);
        }
        mbar_wait((c & 1) ? mb1 : mb0, (c >> 1) & 1);

#pragma unroll
        for (int ks = 0; ks < 2; ks++) {
            uint32_t a[2][4];
#pragma unroll
            for (int mt = 0; mt < 2; mt++) {
                const __half* dr = ds + (mt * 16 + qr) * DS_STRIDE + c * 32 + ks * 16 + 2 * qc;
                a[mt][0] = *reinterpret_cast<const uint32_t*>(dr);
                a[mt][1] = *reinterpret_cast<const uint32_t*>(dr + 8 * DS_STRIDE);
                a[mt][2] = *reinterpret_cast<const uint32_t*>(dr + 8);
                a[mt][3] = *reinterpret_cast<const uint32_t*>(dr + 8 * DS_STRIDE + 8);
            }
#pragma unroll
            for (int nt = 0; nt < 4; nt++) {
                int n0 = warp * 32 + nt * 8 + qr;
                const __half* bp = buf + n0 * STG_R + ks * 16 + 2 * qc;
                uint32_t b0 = *reinterpret_cast<const uint32_t*>(bp);
                uint32_t b1 = *reinterpret_cast<const uint32_t*>(bp + 8);
                mma16(acc2[0][nt], a[0], b0, b1);
                mma16(acc2[1][nt], a[1], b0, b1);
            }
        }
        __syncthreads();
    }

    // ---- write reconstruction
#pragma unroll
    for (int mt = 0; mt < 2; mt++)
#pragma unroll
        for (int nt = 0; nt < 4; nt++) {
            int r0  = mt * 16 + qr;
            int col = warp * 32 + nt * 8 + 2 * qc;
            *reinterpret_cast<float2*>(out + base + (size_t)r0 * D_DIM + col) =
                make_float2(acc2[mt][nt][0], acc2[mt][nt][1]);
            *reinterpret_cast<float2*>(out + base + (size_t)(r0 + 8) * D_DIM + col) =
                make_float2(acc2[mt][nt][2], acc2[mt][nt][3]);
        }
}

// ---------------------------------------------------------------------------
// Kernel 3: finalize loss.  l1 == 1/K exactly.
// entropy = sum_i lse_i - ||colsum||^2 / N
// ---------------------------------------------------------------------------
__global__ void k_loss(float* __restrict__ out, int out_size) {
    __shared__ float red[8];
    int tid = threadIdx.x;
    float s = 0.0f;
    for (int k = tid; k < K_DIM; k += 256) { float c = g_colsum[k]; s += c * c; }
#pragma unroll
    for (int o = 16; o > 0; o >>= 1) s += __shfl_xor_sync(0xffffffffu, s, o);
    if ((tid & 31) == 0) red[tid >> 5] = s;
    __syncthreads();
    if (tid == 0) {
        float t = 0.0f;
#pragma unroll
        for (int w = 0; w < 8; w++) t += red[w];
        float entropy = g_lse_sum - t / (float)N_ROWS;
        float loss = 1000.0f * (1.0f / (float)K_DIM) + 5e-5f * entropy;
        out[out_size - 1] = loss;
    }
}

extern "C" void kernel_launch(void* const* d_in, const int* in_sizes, int n_in,
                              void* d_out, int out_size) {
    const float* in = (const float*)d_in[0];
    const float* cb = (const float*)d_in[1];
    float* out = (float*)d_out;
    (void)in_sizes; (void)n_in;

    const size_t smem = (size_t)(TM * XS_STRIDE + TM * DS_STRIDE + 2 * LBUF_HALFS) * sizeof(__half);
    cudaFuncSetAttribute(k_main, cudaFuncAttributeMaxDynamicSharedMemorySize, (int)smem);

    k_prep<<<K_DIM / 8, 256>>>(cb);
    k_main<<<N_ROWS / TM, NTHR, smem>>>(in, out);
    k_loss<<<1, 256>>>(out, out_size);
}

// round 7
// speedup vs baseline: 7.6594x; 1.4068x over previous
#include <cuda_runtime.h>
#include <cuda_fp16.h>
#include <cstdint>

#define D_DIM 256
#define K_DIM 1024
#define N_ROWS 32768
#define TM 32
#define NTHR 256

// strides in HALFS
#define XS_STRIDE 264          // conflict-free A frags (inputs)
#define DS_STRIDE 1032         // conflict-free A frags / half2 stores (distances)
#define CHUNK_HALFS 32768      // uniform 64 KB chunks (logits: 1024n x 32d; recon: 256d x 128k)
#define CHUNK_BYTES 65536
#define N_LCHUNK 8             // 8 x 32 d
#define N_RCHUNK 8             // 8 x 128 k

// codebook pre-chunked + bank-swizzled for bulk-async streaming (written by k_prep)
__device__ __align__(16) __half g_chunksL[N_LCHUNK * CHUNK_HALFS];  // [dchunk][k=1024][32d sw]
__device__ __align__(16) __half g_chunksR[N_RCHUNK * CHUNK_HALFS];  // [kchunk][d=256][128k sw]
__device__ float g_colsum[K_DIM];
__device__ float g_lse_sum;

__device__ __forceinline__ void mma16(float* c, const uint32_t* a, uint32_t b0, uint32_t b1) {
    asm volatile(
        "mma.sync.aligned.m16n8k16.row.col.f32.f16.f16.f32 "
        "{%0,%1,%2,%3}, {%4,%5,%6,%7}, {%8,%9}, {%0,%1,%2,%3};"
        : "+f"(c[0]), "+f"(c[1]), "+f"(c[2]), "+f"(c[3])
        : "r"(a[0]), "r"(a[1]), "r"(a[2]), "r"(a[3]), "r"(b0), "r"(b1));
}

__device__ __forceinline__ void bulk_cp(uint32_t dst_smem, const void* src,
                                        uint32_t bytes, uint32_t mbar) {
    asm volatile(
        "cp.async.bulk.shared::cta.global.mbarrier::complete_tx::bytes [%0], [%1], %2, [%3];"
        :: "r"(dst_smem), "l"(src), "r"(bytes), "r"(mbar) : "memory");
}
__device__ __forceinline__ void mbar_init(uint32_t mbar, uint32_t cnt) {
    asm volatile("mbarrier.init.shared.b64 [%0], %1;" :: "r"(mbar), "r"(cnt) : "memory");
}
__device__ __forceinline__ void mbar_expect(uint32_t mbar, uint32_t bytes) {
    asm volatile("mbarrier.arrive.expect_tx.shared.b64 _, [%0], %1;"
                 :: "r"(mbar), "r"(bytes) : "memory");
}
__device__ __forceinline__ void mbar_wait(uint32_t mbar, uint32_t parity) {
    asm volatile(
        "{\n\t.reg .pred P;\n\t"
        "WAIT_%=:\n\t"
        "mbarrier.try_wait.parity.acquire.cta.shared::cta.b64 P, [%0], %1, 0x989680;\n\t"
        "@P bra.uni DONE_%=;\n\t"
        "bra.uni WAIT_%=;\n\t"
        "DONE_%=:\n\t}"
        :: "r"(mbar), "r"(parity) : "memory");
}

// ---------------------------------------------------------------------------
// Kernel 1: normalize codebook rows -> fp16, write both swizzled chunk layouts
// Logits row (k): 32 d-halfs = 16 words, rotated by ((k&6)<<1) mod 16.
// Recon  row (d): 128 k-halfs = 64 words, rotated by ((d&7)<<2) mod 64.
// ---------------------------------------------------------------------------
__global__ void k_prep(const float* __restrict__ cb) {
    int lane  = threadIdx.x & 31;
    int gwarp = (blockIdx.x * blockDim.x + threadIdx.x) >> 5;
    if (blockIdx.x == 0) {
        for (int k = threadIdx.x; k < K_DIM; k += blockDim.x) g_colsum[k] = 0.0f;
        if (threadIdx.x == 0) g_lse_sum = 0.0f;
    }
    if (gwarp >= K_DIM) return;
    const int k = gwarp;
    const float* row = cb + (size_t)k * D_DIM;
    float v[8]; float ss = 0.0f;
#pragma unroll
    for (int j = 0; j < 8; j++) { v[j] = row[lane + 32 * j]; ss += v[j] * v[j]; }
#pragma unroll
    for (int o = 16; o > 0; o >>= 1) ss += __shfl_xor_sync(0xffffffffu, ss, o);
    float rinv = rsqrtf(ss);
#pragma unroll
    for (int j = 0; j < 8; j++) {
        int d = lane + 32 * j;
        __half h = __float2half_rn(v[j] * rinv);
        // logits layout
        int cl = d >> 5;
        int wl = ((((d & 31) >> 1) + ((k & 6) << 1)) & 15);
        g_chunksL[cl * CHUNK_HALFS + k * 32 + wl * 2 + (d & 1)] = h;
        // recon layout
        int cr = k >> 7;
        int wr = ((((k & 127) >> 1) + ((d & 7) << 2)) & 63);
        g_chunksR[cr * CHUNK_HALFS + d * 128 + wr * 2 + (k & 1)] = h;
    }
}

// ---------------------------------------------------------------------------
// Kernel 2: fused normalize -> fp16 MMA logits -> fused softmax/stats -> fp16 MMA recon
// One CTA = 32 rows, 8 warps.  8+8 uniform 64KB codebook chunks stream via
// cp.async.bulk into double-buffered SMEM; swizzled rows -> conflict-free LDS.
// ---------------------------------------------------------------------------
extern __shared__ __half s_hbuf[];

__global__ __launch_bounds__(NTHR, 1) void k_main(const float* __restrict__ in,
                                                  float* __restrict__ out) {
    __half* xs  = s_hbuf;                        // [32][264] halfs (normalized inputs)
    __half* ds  = xs + TM * XS_STRIDE;           // [32][1032] halfs (distances)
    __half* stg = ds + TM * DS_STRIDE;           // double-buffered staging (2 x 64 KB)
    __shared__ __align__(8) unsigned long long s_mbar[2];
    __shared__ float s_rowsum[TM];
    __shared__ float s_inv[TM];
    __shared__ float s_t2[TM];
    __shared__ float s_t3[TM];

    const int tid  = threadIdx.x;
    const int warp = tid >> 5, lane = tid & 31;
    const int qr = lane >> 2, qc = lane & 3;
    const size_t base = (size_t)blockIdx.x * TM * D_DIM;

    const uint32_t stg_u32 = (uint32_t)__cvta_generic_to_shared(stg);
    const uint32_t mb0 = (uint32_t)__cvta_generic_to_shared(&s_mbar[0]);
    const uint32_t mb1 = (uint32_t)__cvta_generic_to_shared(&s_mbar[1]);

    if (tid < TM) { s_rowsum[tid] = 0.0f; s_t2[tid] = 0.0f; s_t3[tid] = 0.0f; }
    if (tid == 0) {
        mbar_init(mb0, 1);
        mbar_init(mb1, 1);
        asm volatile("fence.proxy.async.shared::cta;" ::: "memory");
    }
    __syncthreads();

    // issue logits chunk 0 -> buf0 (lands during input load/normalize)
    if (tid == 0) {
        mbar_expect(mb0, CHUNK_BYTES);
        bulk_cp(stg_u32, g_chunksL, CHUNK_BYTES, mb0);
    }

    // load + normalize input rows (warp w -> rows 4w..4w+3) -> fp16 in xs
#pragma unroll
    for (int rr = 0; rr < 4; rr++) {
        int r = warp * 4 + rr;
        const float* rp = in + base + (size_t)r * D_DIM;
        float v[8]; float ss = 0.0f;
#pragma unroll
        for (int j = 0; j < 8; j++) { v[j] = rp[lane + 32 * j]; ss += v[j] * v[j]; }
#pragma unroll
        for (int o = 16; o > 0; o >>= 1) ss += __shfl_xor_sync(0xffffffffu, ss, o);
        float rinv = rsqrtf(ss);
#pragma unroll
        for (int j = 0; j < 8; j++)
            xs[r * XS_STRIDE + lane + 32 * j] = __float2half_rn(v[j] * rinv);
    }
    __syncthreads();

    // ---- logits: L[32,1024] = X @ CT, 8 chunks of 32 d.  warp w: n in [128w,128w+128)
    float acc[2][16][4];
#pragma unroll
    for (int mt = 0; mt < 2; mt++)
#pragma unroll
        for (int nt = 0; nt < 16; nt++)
#pragma unroll
            for (int j = 0; j < 4; j++) acc[mt][nt][j] = 0.0f;

    const int rotL = (qr & 6) << 1;   // logits row rotation (mod 16 words)
    for (int c = 0; c < N_LCHUNK; c++) {
        __half* buf = stg + (c & 1) * CHUNK_HALFS;
        if (tid == 0 && c + 1 < N_LCHUNK) {
            uint32_t b = (c + 1) & 1;
            uint32_t mb = b ? mb1 : mb0;
            mbar_expect(mb, CHUNK_BYTES);
            bulk_cp(stg_u32 + b * CHUNK_BYTES,
                    g_chunksL + (size_t)(c + 1) * CHUNK_HALFS, CHUNK_BYTES, mb);
        }
        mbar_wait((c & 1) ? mb1 : mb0, (c >> 1) & 1);

#pragma unroll
        for (int s = 0; s < 2; s++) {
            uint32_t a[2][4];
#pragma unroll
            for (int mt = 0; mt < 2; mt++) {
                const __half* xr = xs + (mt * 16 + qr) * XS_STRIDE + c * 32 + s * 16 + 2 * qc;
                a[mt][0] = *reinterpret_cast<const uint32_t*>(xr);
                a[mt][1] = *reinterpret_cast<const uint32_t*>(xr + 8 * XS_STRIDE);
                a[mt][2] = *reinterpret_cast<const uint32_t*>(xr + 8);
                a[mt][3] = *reinterpret_cast<const uint32_t*>(xr + 8 * XS_STRIDE + 8);
            }
            const int i0 = ((8 * s + qc + rotL) & 15) << 1;        // b0 half offset in row
            const int i1 = ((8 * s + qc + 4 + rotL) & 15) << 1;    // b1 half offset in row
#pragma unroll
            for (int nt = 0; nt < 16; nt++) {
                int n0 = warp * 128 + nt * 8 + qr;
                const __half* bp = buf + n0 * 32;
                uint32_t b0 = *reinterpret_cast<const uint32_t*>(bp + i0);
                uint32_t b1 = *reinterpret_cast<const uint32_t*>(bp + i1);
                mma16(acc[0][nt], a[0], b0, b1);
                mma16(acc[1][nt], a[1], b0, b1);
            }
        }
        __syncthreads();
    }

    // issue recon chunk 0 -> buf0 (lands during softmax phase); parities continue
    if (tid == 0) {
        mbar_expect(mb0, CHUNK_BYTES);
        bulk_cp(stg_u32, g_chunksR, CHUNK_BYTES, mb0);
    }

    // ---- exp in registers (logits are cosines in [-1,1]: no max pass) + row sums
    float pr[4] = {0.0f, 0.0f, 0.0f, 0.0f};
#pragma unroll
    for (int mt = 0; mt < 2; mt++)
#pragma unroll
        for (int nt = 0; nt < 16; nt++) {
            float e0 = __expf(acc[mt][nt][0]);
            float e1 = __expf(acc[mt][nt][1]);
            float e2 = __expf(acc[mt][nt][2]);
            float e3 = __expf(acc[mt][nt][3]);
            acc[mt][nt][0] = e0; acc[mt][nt][1] = e1;
            acc[mt][nt][2] = e2; acc[mt][nt][3] = e3;
            pr[2 * mt]     += e0 + e1;
            pr[2 * mt + 1] += e2 + e3;
        }
#pragma unroll
    for (int o = 1; o <= 2; o <<= 1)
#pragma unroll
        for (int p = 0; p < 4; p++) pr[p] += __shfl_xor_sync(0xffffffffu, pr[p], o);
    if (qc == 0) {
        atomicAdd(&s_rowsum[qr],      pr[0]);
        atomicAdd(&s_rowsum[qr + 8],  pr[1]);
        atomicAdd(&s_rowsum[qr + 16], pr[2]);
        atomicAdd(&s_rowsum[qr + 24], pr[3]);
    }
    __syncthreads();
    if (tid < TM) s_inv[tid] = 1.0f / s_rowsum[tid];
    __syncthreads();

    // ---- fused: rescale (single fp16 round) -> ds; colsum; Taylor t2/t3
    {
        float iv0 = s_inv[qr], iv1 = s_inv[qr + 8], iv2 = s_inv[qr + 16], iv3 = s_inv[qr + 24];
        float t2[4] = {0, 0, 0, 0}, t3[4] = {0, 0, 0, 0};
#pragma unroll
        for (int nt = 0; nt < 16; nt++) {
            int col = warp * 128 + nt * 8 + 2 * qc;
            float cp0 = 0.0f, cp1 = 0.0f;
#pragma unroll
            for (int mt = 0; mt < 2; mt++) {
                float ivA = (mt == 0) ? iv0 : iv2;
                float ivB = (mt == 0) ? iv1 : iv3;
                float d0 = acc[mt][nt][0] * ivA;
                float d1 = acc[mt][nt][1] * ivA;
                float d2 = acc[mt][nt][2] * ivB;
                float d3 = acc[mt][nt][3] * ivB;
                int r0 = mt * 16 + qr;
                *reinterpret_cast<__half2*>(ds + r0 * DS_STRIDE + col)       = __floats2half2_rn(d0, d1);
                *reinterpret_cast<__half2*>(ds + (r0 + 8) * DS_STRIDE + col) = __floats2half2_rn(d2, d3);
                t2[2 * mt]     += d0 * d0 + d1 * d1;
                t3[2 * mt]     += d0 * d0 * d0 + d1 * d1 * d1;
                t2[2 * mt + 1] += d2 * d2 + d3 * d3;
                t3[2 * mt + 1] += d2 * d2 * d2 + d3 * d3 * d3;
                cp0 += d0 + d2;
                cp1 += d1 + d3;
            }
#pragma unroll
            for (int o = 4; o <= 16; o <<= 1) {
                cp0 += __shfl_xor_sync(0xffffffffu, cp0, o);
                cp1 += __shfl_xor_sync(0xffffffffu, cp1, o);
            }
            if (qr == 0) {
                atomicAdd(&g_colsum[col],     cp0);
                atomicAdd(&g_colsum[col + 1], cp1);
            }
        }
#pragma unroll
        for (int o = 1; o <= 2; o <<= 1)
#pragma unroll
            for (int p = 0; p < 4; p++) {
                t2[p] += __shfl_xor_sync(0xffffffffu, t2[p], o);
                t3[p] += __shfl_xor_sync(0xffffffffu, t3[p], o);
            }
        if (qc == 0) {
#pragma unroll
            for (int p = 0; p < 4; p++) {
                atomicAdd(&s_t2[qr + 8 * p], t2[p]);
                atomicAdd(&s_t3[qr + 8 * p], t3[p]);
            }
        }
    }
    __syncthreads();

    // per-row lse = log(1025 + t2/2 + t3/6); one flush per CTA
    if (tid < TM) {
        float l = __logf(1025.0f + 0.5f * s_t2[tid] + 0.16666667f * s_t3[tid]);
#pragma unroll
        for (int o = 16; o > 0; o >>= 1) l += __shfl_xor_sync(0xffffffffu, l, o);
        if (tid == 0) atomicAdd(&g_lse_sum, l);
    }

    // ---- recon: R[32,256] = dist[32,1024] @ C, 8 chunks of 128 k.  warp w: n in [32w,32w+32)
    float acc2[2][4][4];
#pragma unroll
    for (int mt = 0; mt < 2; mt++)
#pragma unroll
        for (int nt = 0; nt < 4; nt++)
#pragma unroll
            for (int j = 0; j < 4; j++) acc2[mt][nt][j] = 0.0f;

    const int rotR = qr << 2;   // recon row rotation (mod 64 words)
    for (int c = 0; c < N_RCHUNK; c++) {
        __half* buf = stg + (c & 1) * CHUNK_HALFS;
        if (tid == 0 && c + 1 < N_RCHUNK) {
            uint32_t b = (c + 1) & 1;
            uint32_t mb = b ? mb1 : mb0;
            mbar_expect(mb, CHUNK_BYTES);
            bulk_cp(stg_u32 + b * CHUNK_BYTES,
                    g_chunksR + (size_t)(c + 1) * CHUNK_HALFS, CHUNK_BYTES, mb);
        }
        mbar_wait((c & 1) ? mb1 : mb0, (c >> 1) & 1);

#pragma unroll
        for (int ks = 0; ks < 8; ks++) {
            uint32_t a[2][4];
#pragma unroll
            for (int mt = 0; mt < 2; mt++) {
                const __half* dr = ds + (mt * 16 + qr) * DS_STRIDE + c * 128 + ks * 16 + 2 * qc;
                a[mt][0] = *reinterpret_cast<const uint32_t*>(dr);
                a[mt][1] = *reinterpret_cast<const uint32_t*>(dr + 8 * DS_STRIDE);
                a[mt][2] = *reinterpret_cast<const uint32_t*>(dr + 8);
                a[mt][3] = *reinterpret_cast<const uint32_t*>(dr + 8 * DS_STRIDE + 8);
            }
            const int i0 = ((ks * 8 + qc + rotR) & 63) << 1;
            const int i1 = ((ks * 8 + qc + 4 + rotR) & 63) << 1;
#pragma unroll
            for (int nt = 0; nt < 4; nt++) {
                int n0 = warp * 32 + nt * 8 + qr;
                const __half* bp = buf + n0 * 128;
                uint32_t b0 = *reinterpret_cast<const uint32_t*>(bp + i0);
                uint32_t b1 = *reinterpret_cast<const uint32_t*>(bp + i1);
                mma16(acc2[0][nt], a[0], b0, b1);
                mma16(acc2[1][nt], a[1], b0, b1);
            }
        }
        __syncthreads();
    }

    // ---- write reconstruction
#pragma unroll
    for (int mt = 0; mt < 2; mt++)
#pragma unroll
        for (int nt = 0; nt < 4; nt++) {
            int r0  = mt * 16 + qr;
            int col = warp * 32 + nt * 8 + 2 * qc;
            *reinterpret_cast<float2*>(out + base + (size_t)r0 * D_DIM + col) =
                make_float2(acc2[mt][nt][0], acc2[mt][nt][1]);
            *reinterpret_cast<float2*>(out + base + (size_t)(r0 + 8) * D_DIM + col) =
                make_float2(acc2[mt][nt][2], acc2[mt][nt][3]);
        }
}

// ---------------------------------------------------------------------------
// Kernel 3: finalize loss.  l1 == 1/K exactly.
// entropy = sum_i lse_i - ||colsum||^2 / N
// ---------------------------------------------------------------------------
__global__ void k_loss(float* __restrict__ out, int out_size) {
    __shared__ float red[8];
    int tid = threadIdx.x;
    float s = 0.0f;
    for (int k = tid; k < K_DIM; k += 256) { float c = g_colsum[k]; s += c * c; }
#pragma unroll
    for (int o = 16; o > 0; o >>= 1) s += __shfl_xor_sync(0xffffffffu, s, o);
    if ((tid & 31) == 0) red[tid >> 5] = s;
    __syncthreads();
    if (tid == 0) {
        float t = 0.0f;
#pragma unroll
        for (int w = 0; w < 8; w++) t += red[w];
        float entropy = g_lse_sum - t / (float)N_ROWS;
        float loss = 1000.0f * (1.0f / (float)K_DIM) + 5e-5f * entropy;
        out[out_size - 1] = loss;
    }
}

extern "C" void kernel_launch(void* const* d_in, const int* in_sizes, int n_in,
                              void* d_out, int out_size) {
    const float* in = (const float*)d_in[0];
    const float* cb = (const float*)d_in[1];
    float* out = (float*)d_out;
    (void)in_sizes; (void)n_in;

    const size_t smem = (size_t)(TM * XS_STRIDE + TM * DS_STRIDE + 2 * CHUNK_HALFS) * sizeof(__half);
    cudaFuncSetAttribute(k_main, cudaFuncAttributeMaxDynamicSharedMemorySize, (int)smem);

    k_prep<<<K_DIM / 8, 256>>>(cb);
    k_main<<<N_ROWS / TM, NTHR, smem>>>(in, out);
    k_loss<<<1, 256>>>(out, out_size);
}